// round 11
// baseline (speedup 1.0000x reference)
#include <cuda_runtime.h>
#include <cstdint>

// NN_16_1_Pooling: x[16,64,224,224] f32 -> per 2x2 patch MLP (4->16 relu ->1)
// -> out[16,64,112,112] f32.
//
// R11: R10's 24 volatile LDS/iter sat 1-3 instrs ahead of their consumers
// (exposed ~26cyc x 8 hp groups -> issue capped at 54%). Now the per-hp
// weight stream is software-pipelined: wreg[2][6] double buffer, hp+1's
// 3x ld.shared.v2.b64 issued BEFORE hp's 28-instr compute body -> every
// LDS->consumer distance > smem latency. bias2 pack hoisted. Everything
// else (4 CTAs/SM, 3-buffer LDG.128 ring, exact 56x56x24 mapping) is R10.

typedef unsigned long long u64;

#define W4 56                          // input row pitch in float4
#define IN_STEP (24 * 224 * 56)        // 24 planes, float4 units
#define OUT_STEP (24 * 112 * 56)       // 24 planes, float2 units
#define OUT_PITCH2 56                  // output row pitch in float2

__device__ __forceinline__ u64 pk2(float lo, float hi) {
    u64 r;
    asm("mov.b64 %0, {%1, %2};" : "=l"(r) : "f"(lo), "f"(hi));
    return r;
}
__device__ __forceinline__ u64 fma2(u64 a, u64 b, u64 c) {
    u64 d;
    asm("fma.rn.f32x2 %0, %1, %2, %3;" : "=l"(d) : "l"(a), "l"(b), "l"(c));
    return d;
}
__device__ __forceinline__ float2 upk(u64 v) {
    float lo, hi;
    asm("mov.b64 {%0, %1}, %2;" : "=f"(lo), "=f"(hi) : "l"(v));
    return make_float2(lo, hi);
}
__device__ __forceinline__ void lds128(u64& a, u64& b, uint32_t addr) {
    asm volatile("ld.shared.v2.b64 {%0, %1}, [%2];" : "=l"(a), "=l"(b) : "r"(addr));
}

__device__ __forceinline__ void load4(float4* v, const float4* __restrict__ p) {
    v[0] = __ldg(p);
    v[1] = __ldg(p + W4);
    v[2] = __ldg(p + 2 * W4);
    v[3] = __ldg(p + 3 * W4);
}

// 4 patches (2 row-pairs); per-hp weights streamed with 1-stage lookahead.
__device__ __forceinline__ void compute_store(const float4* v, uint32_t wa,
                                              u64 bias2p,
                                              float2* __restrict__ op) {
    // Broadcast x packs: xp[p][k] = {k_val, k_val}
    u64 xp[4][4];
    #pragma unroll
    for (int rp = 0; rp < 2; rp++) {
        const float4 tt = v[2 * rp];
        const float4 uu = v[2 * rp + 1];
        xp[2 * rp + 0][0] = pk2(tt.x, tt.x);
        xp[2 * rp + 0][1] = pk2(tt.y, tt.y);
        xp[2 * rp + 0][2] = pk2(uu.x, uu.x);
        xp[2 * rp + 0][3] = pk2(uu.y, uu.y);
        xp[2 * rp + 1][0] = pk2(tt.z, tt.z);
        xp[2 * rp + 1][1] = pk2(tt.w, tt.w);
        xp[2 * rp + 1][2] = pk2(uu.z, uu.z);
        xp[2 * rp + 1][3] = pk2(uu.w, uu.w);
    }

    u64 acc[4];
    #pragma unroll
    for (int p = 0; p < 4; p++) acc[p] = bias2p;

    // Double-buffered weight stream: wreg[hp&1] in use, wreg[(hp+1)&1] filling.
    u64 wreg[2][6];   // {w1k0, w1k1, w1k2, w1k3, b1, w2}
    lds128(wreg[0][0], wreg[0][1], wa);
    lds128(wreg[0][2], wreg[0][3], wa + 16);
    lds128(wreg[0][4], wreg[0][5], wa + 32);

    #pragma unroll
    for (int hp = 0; hp < 8; hp++) {
        const int cur = hp & 1, nxt = cur ^ 1;
        if (hp < 7) {
            const uint32_t a = wa + (hp + 1) * 64;
            lds128(wreg[nxt][0], wreg[nxt][1], a);
            lds128(wreg[nxt][2], wreg[nxt][3], a + 16);
            lds128(wreg[nxt][4], wreg[nxt][5], a + 32);
        }
        #pragma unroll
        for (int p = 0; p < 4; p++) {
            u64 h2 = fma2(wreg[cur][0], xp[p][0], wreg[cur][4]);
            h2 = fma2(wreg[cur][1], xp[p][1], h2);
            h2 = fma2(wreg[cur][2], xp[p][2], h2);
            h2 = fma2(wreg[cur][3], xp[p][3], h2);
            const float2 hv = upk(h2);
            const u64 rl = pk2(fmaxf(hv.x, 0.0f), fmaxf(hv.y, 0.0f));
            acc[p] = fma2(wreg[cur][5], rl, acc[p]);
        }
    }

    const float2 a0 = upk(acc[0]);
    const float2 a1 = upk(acc[1]);
    const float2 a2 = upk(acc[2]);
    const float2 a3 = upk(acc[3]);
    op[0]          = make_float2(a0.x + a0.y, a1.x + a1.y);
    op[OUT_PITCH2] = make_float2(a2.x + a2.y, a3.x + a3.y);
}

__global__ __launch_bounds__(128, 4)
void mlp_pool_kernel(const float* __restrict__ x,
                     const float* __restrict__ W1,
                     const float* __restrict__ b1,
                     const float* __restrict__ W2,
                     const float* __restrict__ b2,
                     float* __restrict__ out)
{
    // s_wp[hp] = {w1p[k0..k3], b1p, w2p} padded to 64B
    __shared__ u64 s_wp[8][8];
    __shared__ float s_b2;
    if (threadIdx.x < 8) {
        const int hp = threadIdx.x;
        #pragma unroll
        for (int k = 0; k < 4; k++)
            s_wp[hp][k] = pk2(__ldg(W1 + (2 * hp) * 4 + k),
                              __ldg(W1 + (2 * hp + 1) * 4 + k));
        s_wp[hp][4] = pk2(__ldg(b1 + 2 * hp), __ldg(b1 + 2 * hp + 1));
        s_wp[hp][5] = pk2(__ldg(W2 + 2 * hp), __ldg(W2 + 2 * hp + 1));
        if (hp == 0) s_b2 = __ldg(b2);
    }
    __syncthreads();
    const u64 bias2p = pk2(s_b2, 0.0f);
    const uint32_t wa = (uint32_t)__cvta_generic_to_shared(s_wp);

    // 75264 threads = 56(j) x 56(q) x 24(c0); j,q fixed, chan += 24.
    const int tid = blockIdx.x * blockDim.x + threadIdx.x;
    const int j = tid % 56;
    const int t = tid / 56;
    const int q = t % 56;                   // output double-row
    const int c0 = t / 56;                  // 0..23
    const int n = (1023 - c0) / 24 + 1;     // 43 (c0<=15) or 42

    const float4* ip = (const float4*)x + c0 * (224 * 56) + (4 * q) * W4 + j;
    float2* op = (float2*)out + c0 * (112 * 56) + (2 * q) * OUT_PITCH2 + j;

    float4 va[4], vb[4], vc[4];

    // Prologue: stages 0,1.
    load4(va, ip); ip += IN_STEP;
    load4(vb, ip); ip += IN_STEP;

    // Guard-free main: 39 iterations = 13 x 3-stage ring blocks.
    for (int blk = 0; blk < 13; blk++) {
        load4(vc, ip); ip += IN_STEP;
        compute_store(va, wa, bias2p, op); op += OUT_STEP;
        load4(va, ip); ip += IN_STEP;
        compute_store(vb, wa, bias2p, op); op += OUT_STEP;
        load4(vb, ip); ip += IN_STEP;
        compute_store(vc, wa, bias2p, op); op += OUT_STEP;
    }

    // Tail: va=stage 39, vb=stage 40; ip -> stage 41 (always valid).
    load4(vc, ip); ip += IN_STEP;                         // 41
    compute_store(va, wa, bias2p, op); op += OUT_STEP;    // 39
    if (n > 42) load4(va, ip);                            // 42 (c0<=15)
    compute_store(vb, wa, bias2p, op); op += OUT_STEP;    // 40
    compute_store(vc, wa, bias2p, op); op += OUT_STEP;    // 41
    if (n > 42) compute_store(va, wa, bias2p, op);        // 42
}

extern "C" void kernel_launch(void* const* d_in, const int* in_sizes, int n_in,
                              void* d_out, int out_size)
{
    const float* x  = (const float*)d_in[0];
    const float* W1 = (const float*)d_in[1];
    const float* b1 = (const float*)d_in[2];
    const float* W2 = (const float*)d_in[3];
    const float* b2 = (const float*)d_in[4];
    float* out = (float*)d_out;

    // 588 blocks x 128 threads = 75264 = 56 * 56 * 24; 4 CTAs/SM.
    mlp_pool_kernel<<<588, 128>>>(x, W1, b1, W2, b2, out);
}